// round 14
// baseline (speedup 1.0000x reference)
#include <cuda_runtime.h>
#include <cuda_fp16.h>
#include <cstdint>

#define N_NODES 100000
#define N_EDGES 3200000
#define N_FEAT  512
#define N_HID   256

typedef unsigned long long u64;

// ---------------- static scratch (no allocation allowed) ----------------
__device__ uint32_t d_hh[(size_t)N_NODES * (N_HID / 2)];   // FC output, fp16x2
__device__ float d_g[(size_t)N_NODES * N_HID];             // post-SpMM/PReLU (graph 1 only)
__device__ int   d_rowptr[N_NODES + 1];
__device__ int   d_cursor[N_NODES];
__device__ int   d_colidx[N_EDGES];
__device__ float d_eval[N_EDGES];
__device__ int   d_bsum[128];
__device__ float d_colsum[N_HID];
__device__ float d_v[N_HID];
__device__ int   d_is32;
// W as fp16 hi/lo, pair-permuted, [N_HID][256] u32
__device__ uint32_t d_whp[N_HID * (N_FEAT / 2)];
__device__ uint32_t d_wlp[N_HID * (N_FEAT / 2)];

// ---------------- helpers ----------------
__device__ __forceinline__ uint32_t smem_u32p(const void* p) {
    uint32_t a;
    asm("{ .reg .u64 t; cvta.to.shared.u64 t, %1; cvt.u32.u64 %0, t; }" : "=r"(a) : "l"(p));
    return a;
}
__device__ __forceinline__ void cpa16(uint32_t dst, const void* src) {
    asm volatile("cp.async.cg.shared.global [%0], [%1], 16;" :: "r"(dst), "l"(src));
}
__device__ __forceinline__ void cpa_commit() {
    asm volatile("cp.async.commit_group;" ::: "memory");
}
__device__ __forceinline__ void mma_f16(float* c, const uint32_t* a, const uint32_t* b) {
    asm volatile("mma.sync.aligned.m16n8k16.row.col.f32.f16.f16.f32 "
        "{%0,%1,%2,%3}, {%4,%5,%6,%7}, {%8,%9}, {%0,%1,%2,%3};"
        : "+f"(c[0]), "+f"(c[1]), "+f"(c[2]), "+f"(c[3])
        : "r"(a[0]), "r"(a[1]), "r"(a[2]), "r"(a[3]), "r"(b[0]), "r"(b[1]));
}

__device__ __forceinline__ int warp_incl_scan(int v) {
    int lane = threadIdx.x & 31;
#pragma unroll
    for (int o = 1; o < 32; o <<= 1) {
        int t = __shfl_up_sync(0xffffffffu, v, o);
        if (lane >= o) v += t;
    }
    return v;
}
__device__ __forceinline__ int block_incl_scan(int v, int* smem) {
    int lane = threadIdx.x & 31;
    int wid  = threadIdx.x >> 5;
    int nw   = blockDim.x >> 5;
    int s = warp_incl_scan(v);
    if (lane == 31) smem[wid] = s;
    __syncthreads();
    if (wid == 0) {
        int t = (lane < nw) ? smem[lane] : 0;
        t = warp_incl_scan(t);
        if (lane < nw) smem[lane] = t;
    }
    __syncthreads();
    int add = (wid > 0) ? smem[wid - 1] : 0;
    return s + add;
}
__device__ __forceinline__ int edge_at(const void* eidx, size_t idx) {
    if (d_is32) return ((const int*)eidx)[idx];
    return (int)((const long long*)eidx)[idx];
}

// fp32 x16 -> fp16 hi/lo pair-permuted x8
__device__ __forceinline__ void cvt16(const float* v, uint32_t* hp, uint32_t* lq) {
#pragma unroll
    for (int p = 0; p < 8; p++) {
        __half h0 = __float2half_rn(v[2 * p]);
        __half h1 = __float2half_rn(v[2 * p + 1]);
        float r0 = v[2 * p] - __half2float(h0);
        float r1 = v[2 * p + 1] - __half2float(h1);
        __half l0 = __float2half_rn(r0);
        __half l1 = __float2half_rn(r1);
        hp[p] = (uint32_t)__half_as_ushort(h0) | ((uint32_t)__half_as_ushort(h1) << 16);
        lq[p] = (uint32_t)__half_as_ushort(l0) | ((uint32_t)__half_as_ushort(l1) << 16);
    }
}

// ---------------- dtype detection ----------------
__global__ void detect_kernel(const void* eidx) {
    if (threadIdx.x == 0 && blockIdx.x == 0) {
        const long long* p = (const long long*)eidx;
        int is32 = 0;
        for (int i = 0; i < 64; i++) {
            long long v = p[i];
            if (v < 0 || v >= (long long)N_NODES) { is32 = 1; break; }
        }
        d_is32 = is32;
    }
}

// ---------------- W -> fp16 hi/lo, pair-permuted ----------------
__global__ void wcvt_kernel(const float* __restrict__ W) {
    int gid = blockIdx.x * blockDim.x + threadIdx.x;
    if (gid >= N_HID * (N_FEAT / 16)) return;
    float v[16];
#pragma unroll
    for (int i = 0; i < 4; i++) {
        float4 t = ((const float4*)(W + (size_t)gid * 16))[i];
        v[4 * i] = t.x; v[4 * i + 1] = t.y; v[4 * i + 2] = t.z; v[4 * i + 3] = t.w;
    }
    uint32_t hp[8], lq[8];
    cvt16(v, hp, lq);
    uint4* dh = (uint4*)d_whp + (size_t)gid * 2;
    uint4* dl = (uint4*)d_wlp + (size_t)gid * 2;
    dh[0] = make_uint4(hp[0], hp[4], hp[1], hp[5]);
    dh[1] = make_uint4(hp[2], hp[6], hp[3], hp[7]);
    dl[0] = make_uint4(lq[0], lq[4], lq[1], lq[5]);
    dl[1] = make_uint4(lq[2], lq[6], lq[3], lq[7]);
}

// ---------------- graph build ----------------
__global__ void zero_kernel() {
    int i = blockIdx.x * blockDim.x + threadIdx.x;
    if (i < N_NODES) d_cursor[i] = 0;
    if (i < N_HID)   d_colsum[i] = 0.f;
}
__global__ void hist_kernel(const void* __restrict__ eidx) {
    int e = blockIdx.x * blockDim.x + threadIdx.x;
    if (e < N_EDGES) {
        int r = edge_at(eidx, (size_t)e);
        if ((unsigned)r < (unsigned)N_NODES)
            atomicAdd(&d_cursor[r], 1);
    }
}
__global__ void scan1_kernel() {
    __shared__ int smem[32];
    int i = blockIdx.x * 1024 + threadIdx.x;
    int c = (i < N_NODES) ? d_cursor[i] : 0;
    int s = block_incl_scan(c, smem);
    if (threadIdx.x == 1023) d_bsum[blockIdx.x] = s;
}
__global__ void scan2_kernel(int nblocks) {
    __shared__ int smem[32];
    int t = threadIdx.x;
    int v = (t < nblocks) ? d_bsum[t] : 0;
    int s = block_incl_scan(v, smem);
    if (t < nblocks) d_bsum[t] = s - v;  // exclusive
}
__global__ void scan3_kernel() {
    __shared__ int smem[32];
    int i = blockIdx.x * 1024 + threadIdx.x;
    int c = (i < N_NODES) ? d_cursor[i] : 0;
    int s = block_incl_scan(c, smem);
    int base = d_bsum[blockIdx.x];
    if (i < N_NODES) {
        int end = base + s;
        d_rowptr[i + 1] = end;
        d_cursor[i] = end - c;
    }
    if (i == 0) d_rowptr[0] = 0;
}
__global__ void scatter_kernel(const void* __restrict__ eidx,
                               const float* __restrict__ evals) {
    int e = blockIdx.x * blockDim.x + threadIdx.x;
    if (e < N_EDGES) {
        int r = edge_at(eidx, (size_t)e);
        int c = edge_at(eidx, (size_t)N_EDGES + e);
        if ((unsigned)r >= (unsigned)N_NODES) return;
        if ((unsigned)c >= (unsigned)N_NODES) c = 0;
        int p = atomicAdd(&d_cursor[r], 1);
        if ((unsigned)p < (unsigned)N_EDGES) {
            d_colidx[p] = c;
            d_eval[p]   = evals[e];
        }
    }
}

// ---------------- GEMM: mma.sync f16 3-term split, fp32 A staged + converted in-kernel ----------------
// smem u32 layout: AF[2][128*36] | AH[3072] | AL[3072] | BH[2][3072] | BL[2][3072]
#define SROW 24
#define AFS 36
#define AF_U (128 * AFS)      // 4608
#define ABUF 3072             // 128 * SROW
__global__ void __launch_bounds__(256, 1)
gemm_mma_kernel(const float* __restrict__ A, const float* __restrict__ bias) {
    extern __shared__ uint32_t sm[];
    uint32_t* AF = sm;                       // [2][AF_U]
    uint32_t* AH = sm + 2 * AF_U;            // [ABUF]
    uint32_t* AL = AH + ABUF;                // [ABUF]
    uint32_t* BH = AL + ABUF;                // [2][ABUF]
    uint32_t* BL = BH + 2 * ABUF;            // [2][ABUF]
    const uint32_t sbase = smem_u32p(sm);
    const uint32_t bh_base = sbase + (uint32_t)(2 * AF_U + 2 * ABUF) * 4;
    const uint32_t bl_off  = (uint32_t)(2 * ABUF) * 4;

    const int tid = threadIdx.x, lane = tid & 31, wid = tid >> 5;
    const int m0 = blockIdx.y * 128, n0 = blockIdx.x * 128;
    const int g = lane >> 2, tq = lane & 3;
    const int wm = (wid >> 1) * 32, wn = (wid & 1) * 64;

    // loader mapping: 2 threads per row
    const int lr = tid >> 1;
    const int lp = tid & 1;
    int arow = m0 + lr; if (arow >= N_NODES) arow = N_NODES - 1;
    const float*    ag  = A + (size_t)arow * N_FEAT + lp * 16;
    const uint32_t* bgh = d_whp + (size_t)(n0 + lr) * 256 + lp * 8;
    const uint32_t* bgl = d_wlp + (size_t)(n0 + lr) * 256 + lp * 8;
    const uint32_t af_dst = (uint32_t)(lr * AFS + lp * 16) * 4;   // byte off in AF buffer
    const uint32_t b_dst  = (uint32_t)(lr * SROW + lp * 8) * 4;   // byte off in B buffer

    float acc[2][8][4];
#pragma unroll
    for (int mt = 0; mt < 2; mt++)
#pragma unroll
        for (int nt = 0; nt < 8; nt++)
#pragma unroll
            for (int c = 0; c < 4; c++) acc[mt][nt][c] = 0.f;

#define PREFETCH(kc, b) do { \
    uint32_t ao = sbase + (uint32_t)(b) * (AF_U * 4) + af_dst; \
    const float* asrc = ag + (kc) * 32; \
    cpa16(ao, asrc); cpa16(ao + 16, asrc + 4); \
    cpa16(ao + 32, asrc + 8); cpa16(ao + 48, asrc + 12); \
    uint32_t bo = bh_base + (uint32_t)(b) * (ABUF * 4) + b_dst; \
    const uint32_t ksrc = (uint32_t)(kc) * 16; \
    cpa16(bo, bgh + ksrc); cpa16(bo + 16, bgh + ksrc + 4); \
    cpa16(bo + bl_off, bgl + ksrc); cpa16(bo + bl_off + 16, bgl + ksrc + 4); \
} while (0)

    PREFETCH(0, 0);
    cpa_commit();

    for (int kc = 0; kc < N_FEAT / 32; kc++) {
        if (kc < N_FEAT / 32 - 1) {
            PREFETCH(kc + 1, (kc + 1) & 1);
            cpa_commit();
            asm volatile("cp.async.wait_group 1;" ::: "memory");
        } else {
            asm volatile("cp.async.wait_group 0;" ::: "memory");
        }
        __syncthreads();

        // ---- convert this chunk's fp32 A -> fp16 hi/lo (pair-permuted) ----
        {
            const float* afp = (const float*)(AF + (kc & 1) * AF_U + lr * AFS + lp * 16);
            float v[16];
#pragma unroll
            for (int i = 0; i < 4; i++) {
                float4 t = ((const float4*)afp)[i];
                v[4 * i] = t.x; v[4 * i + 1] = t.y; v[4 * i + 2] = t.z; v[4 * i + 3] = t.w;
            }
            uint32_t hp[8], lq[8];
            cvt16(v, hp, lq);
            uint2* oh = (uint2*)(AH + lr * SROW + lp * 8);
            uint2* ol = (uint2*)(AL + lr * SROW + lp * 8);
            oh[0] = make_uint2(hp[0], hp[4]); oh[1] = make_uint2(hp[1], hp[5]);
            oh[2] = make_uint2(hp[2], hp[6]); oh[3] = make_uint2(hp[3], hp[7]);
            ol[0] = make_uint2(lq[0], lq[4]); ol[1] = make_uint2(lq[1], lq[5]);
            ol[2] = make_uint2(lq[2], lq[6]); ol[3] = make_uint2(lq[3], lq[7]);
        }
        __syncthreads();

        const uint32_t bb = (uint32_t)(kc & 1) * ABUF;
#pragma unroll
        for (int kk = 0; kk < 2; kk++) {
            const int kb = kk * 8 + 2 * tq;
            uint32_t ah[2][4], al[2][4], bh[8][2], bl[8][2];
#pragma unroll
            for (int mt = 0; mt < 2; mt++) {
                int r = wm + mt * 16 + g;
                u64 t0 = *(const u64*)(AH + r * SROW + kb);
                u64 t1 = *(const u64*)(AH + (r + 8) * SROW + kb);
                ah[mt][0] = (uint32_t)t0; ah[mt][2] = (uint32_t)(t0 >> 32);
                ah[mt][1] = (uint32_t)t1; ah[mt][3] = (uint32_t)(t1 >> 32);
                u64 s0 = *(const u64*)(AL + r * SROW + kb);
                u64 s1 = *(const u64*)(AL + (r + 8) * SROW + kb);
                al[mt][0] = (uint32_t)s0; al[mt][2] = (uint32_t)(s0 >> 32);
                al[mt][1] = (uint32_t)s1; al[mt][3] = (uint32_t)(s1 >> 32);
            }
#pragma unroll
            for (int nt = 0; nt < 8; nt++) {
                int r = wn + nt * 8 + g;
                u64 t = *(const u64*)(BH + bb + r * SROW + kb);
                bh[nt][0] = (uint32_t)t; bh[nt][1] = (uint32_t)(t >> 32);
                u64 s = *(const u64*)(BL + bb + r * SROW + kb);
                bl[nt][0] = (uint32_t)s; bl[nt][1] = (uint32_t)(s >> 32);
            }
#pragma unroll
            for (int mt = 0; mt < 2; mt++)
#pragma unroll
                for (int nt = 0; nt < 8; nt++) {
                    mma_f16(acc[mt][nt], ah[mt], bh[nt]);
                    mma_f16(acc[mt][nt], al[mt], bh[nt]);
                    mma_f16(acc[mt][nt], ah[mt], bl[nt]);
                }
        }
        __syncthreads();
    }
#undef PREFETCH

    // epilogue: bias add then pack fp16x2 into d_hh
#pragma unroll
    for (int mt = 0; mt < 2; mt++) {
        int r0 = m0 + wm + mt * 16 + g;
        int r1 = r0 + 8;
#pragma unroll
        for (int nt = 0; nt < 8; nt++) {
            int col = n0 + wn + nt * 8 + 2 * tq;
            float2 b = *(const float2*)&bias[col];
            int pidx = col >> 1;
            if (r0 < N_NODES) {
                __half2 o = __floats2half2_rn(acc[mt][nt][0] + b.x, acc[mt][nt][1] + b.y);
                d_hh[(size_t)r0 * (N_HID / 2) + pidx] = *(uint32_t*)&o;
            }
            if (r1 < N_NODES) {
                __half2 o = __floats2half2_rn(acc[mt][nt][2] + b.x, acc[mt][nt][3] + b.y);
                d_hh[(size_t)r1 * (N_HID / 2) + pidx] = *(uint32_t*)&o;
            }
        }
    }
}

// ---------------- SpMM body (fp16 gather, fp32 accumulate) ----------------
__device__ __forceinline__ void spmm_row(int node, int j, float a0, float& ax, float& ay) {
    const int beg = d_rowptr[node];
    const int end = d_rowptr[node + 1];
    ax = 0.f; ay = 0.f;
    int e = beg;
    for (; e + 4 <= end; e += 4) {
        int c0 = d_colidx[e], c1 = d_colidx[e + 1];
        int c2 = d_colidx[e + 2], c3 = d_colidx[e + 3];
        float w0 = d_eval[e], w1 = d_eval[e + 1];
        float w2 = d_eval[e + 2], w3 = d_eval[e + 3];
        uint32_t p0 = d_hh[(size_t)c0 * (N_HID / 2) + j];
        uint32_t p1 = d_hh[(size_t)c1 * (N_HID / 2) + j];
        uint32_t p2 = d_hh[(size_t)c2 * (N_HID / 2) + j];
        uint32_t p3 = d_hh[(size_t)c3 * (N_HID / 2) + j];
        float2 v0 = __half22float2(*(__half2*)&p0);
        float2 v1 = __half22float2(*(__half2*)&p1);
        float2 v2 = __half22float2(*(__half2*)&p2);
        float2 v3 = __half22float2(*(__half2*)&p3);
        ax += w0 * v0.x; ay += w0 * v0.y;
        ax += w1 * v1.x; ay += w1 * v1.y;
        ax += w2 * v2.x; ay += w2 * v2.y;
        ax += w3 * v3.x; ay += w3 * v3.y;
    }
    for (; e < end; ++e) {
        int c = d_colidx[e];
        float w = d_eval[e];
        uint32_t p = d_hh[(size_t)c * (N_HID / 2) + j];
        float2 v = __half22float2(*(__half2*)&p);
        ax += w * v.x; ay += w * v.y;
    }
    ax = (ax >= 0.f) ? ax : a0 * ax;
    ay = (ay >= 0.f) ? ay : a0 * ay;
}

// graph 1: write g
__global__ __launch_bounds__(128)
void spmm_kernel(const float* __restrict__ prelu_a) {
    const int node = blockIdx.x;
    const int j = threadIdx.x;
    float ax, ay;
    spmm_row(node, j, prelu_a[0], ax, ay);
    *(float2*)&d_g[(size_t)node * N_HID + 2 * j] = make_float2(ax, ay);
}

// graph 2: fused score (v already computed from graph 1)
__global__ __launch_bounds__(128)
void spmm_score_kernel(const float* __restrict__ prelu_a,
                       const float* __restrict__ bb, float* __restrict__ out) {
    __shared__ float red[4];
    const int node = blockIdx.x;
    const int j = threadIdx.x;
    const int lane = j & 31, warp = j >> 5;
    float ax, ay;
    spmm_row(node, j, prelu_a[0], ax, ay);
    float2 vv = *(const float2*)&d_v[2 * j];
    float dot = ax * vv.x + ay * vv.y;
#pragma unroll
    for (int o = 16; o > 0; o >>= 1) dot += __shfl_xor_sync(0xffffffffu, dot, o);
    if (lane == 0) red[warp] = dot;
    __syncthreads();
    if (j == 0) out[node] = red[0] + red[1] + red[2] + red[3] + bb[0];
}

// ---------------- column sum / v / score (graph 1) ----------------
__global__ void colsum_kernel() {
    const int j = threadIdx.x;
    const int start = blockIdx.x * 512;
    int stop = start + 512;
    if (stop > N_NODES) stop = N_NODES;
    float s = 0.f;
    for (int n = start; n < stop; n++) s += d_g[(size_t)n * N_HID + j];
    atomicAdd(&d_colsum[j], s);
}
__global__ void vker(const float* __restrict__ bw) {
    __shared__ float ssig[N_HID];
    int t = threadIdx.x;
    ssig[t] = 1.f / (1.f + expf(-d_colsum[t] * (1.f / (float)N_NODES)));
    __syncthreads();
    float acc = 0.f;
#pragma unroll 8
    for (int g = 0; g < N_HID; g++) acc += bw[t * N_HID + g] * ssig[g];
    d_v[t] = acc;
}
__global__ __launch_bounds__(256)
void score_kernel(const float* __restrict__ bb, float* __restrict__ out) {
    const int warp = threadIdx.x >> 5;
    const int lane = threadIdx.x & 31;
    const int node = blockIdx.x * 8 + warp;
    if (node >= N_NODES) return;
    const float4* gr = (const float4*)&d_g[(size_t)node * N_HID];
    const float4* vv = (const float4*)d_v;
    float acc = 0.f;
#pragma unroll
    for (int i = lane; i < 64; i += 32) {
        float4 a = gr[i];
        float4 b = vv[i];
        acc += a.x * b.x + a.y * b.y + a.z * b.z + a.w * b.w;
    }
#pragma unroll
    for (int o = 16; o > 0; o >>= 1) acc += __shfl_xor_sync(0xffffffffu, acc, o);
    if (lane == 0) out[node] = acc + bb[0];
}

// ---------------- launch ----------------
extern "C" void kernel_launch(void* const* d_in, const int* in_sizes, int n_in,
                              void* d_out, int out_size) {
    const float* x1  = (const float*)d_in[0];
    const float* x2  = (const float*)d_in[1];
    const float* ev  = (const float*)d_in[2];
    const float* fcw = (const float*)d_in[3];
    const float* fcb = (const float*)d_in[4];
    const float* pa  = (const float*)d_in[5];
    const float* bw  = (const float*)d_in[6];
    const float* bb  = (const float*)d_in[7];
    const void*  ei  = (const void*)d_in[8];
    float* out = (float*)d_out;

    const int GEMM_SMEM = (2 * AF_U + 2 * ABUF + 4 * ABUF) * 4;   // 110592 bytes
    static int smem_set = 0;
    if (!smem_set) {
        cudaFuncSetAttribute(gemm_mma_kernel,
                             cudaFuncAttributeMaxDynamicSharedMemorySize, GEMM_SMEM);
        smem_set = 1;
    }

    const int scan_blocks = (N_NODES + 1023) / 1024;
    const int edge_blocks = (N_EDGES + 255) / 256;
    const int wgrp_blocks = (N_HID * (N_FEAT / 16) + 255) / 256;
    dim3 ggrid(N_HID / 128, (N_NODES + 127) / 128);

    // CSR build + W conversion
    detect_kernel<<<1, 32>>>(ei);
    wcvt_kernel<<<wgrp_blocks, 256>>>(fcw);
    zero_kernel<<<(N_NODES + 255) / 256, 256>>>();
    hist_kernel<<<edge_blocks, 256>>>(ei);
    scan1_kernel<<<scan_blocks, 1024>>>();
    scan2_kernel<<<1, 128>>>(scan_blocks);
    scan3_kernel<<<scan_blocks, 1024>>>();
    scatter_kernel<<<edge_blocks, 256>>>(ei, ev);

    // graph 1
    gemm_mma_kernel<<<ggrid, 256, GEMM_SMEM>>>(x1, fcb);
    spmm_kernel<<<N_NODES, 128>>>(pa);
    colsum_kernel<<<(N_NODES + 511) / 512, 256>>>();
    vker<<<1, N_HID>>>(bw);
    score_kernel<<<(N_NODES + 7) / 8, 256>>>(bb, out);

    // graph 2 (fused spmm+score; no d_g traffic)
    gemm_mma_kernel<<<ggrid, 256, GEMM_SMEM>>>(x2, fcb);
    spmm_score_kernel<<<N_NODES, 128>>>(pa, bb, out + N_NODES);
}

// round 17
// speedup vs baseline: 1.0274x; 1.0274x over previous
#include <cuda_runtime.h>
#include <cuda_fp16.h>
#include <cstdint>

#define N_NODES 100000
#define N_EDGES 3200000
#define N_FEAT  512
#define N_HID   256

typedef unsigned long long u64;

// ---------------- static scratch (no allocation allowed) ----------------
__device__ uint32_t d_hh[(size_t)N_NODES * (N_HID / 2)];   // FC output, fp16x2
__device__ uint32_t d_gh[(size_t)N_NODES * (N_HID / 2)];   // graph-1 g, fp16x2
__device__ int   d_rowptr[N_NODES + 1];
__device__ int   d_cursor[N_NODES];
__device__ int   d_colidx[N_EDGES];
__device__ float d_eval[N_EDGES];
__device__ int   d_bsum[128];
__device__ float d_colsum[N_HID];
__device__ float d_v[N_HID];
__device__ int   d_is32;
// A as fp16 hi/lo, pair-permuted, [N_NODES][256] u32 (2 fp16 per u32)
__device__ uint32_t d_ah[(size_t)N_NODES * (N_FEAT / 2)];
__device__ uint32_t d_al[(size_t)N_NODES * (N_FEAT / 2)];
// W as fp16 hi/lo, pair-permuted, [N_HID][256] u32
__device__ uint32_t d_whp[N_HID * (N_FEAT / 2)];
__device__ uint32_t d_wlp[N_HID * (N_FEAT / 2)];

// ---------------- helpers ----------------
__device__ __forceinline__ uint32_t smem_u32p(const void* p) {
    uint32_t a;
    asm("{ .reg .u64 t; cvta.to.shared.u64 t, %1; cvt.u32.u64 %0, t; }" : "=r"(a) : "l"(p));
    return a;
}
__device__ __forceinline__ void cpa16(uint32_t dst, const void* src) {
    asm volatile("cp.async.cg.shared.global [%0], [%1], 16;" :: "r"(dst), "l"(src));
}
__device__ __forceinline__ void cpa_commit() {
    asm volatile("cp.async.commit_group;" ::: "memory");
}
__device__ __forceinline__ void mma_f16(float* c, const uint32_t* a, const uint32_t* b) {
    asm volatile("mma.sync.aligned.m16n8k16.row.col.f32.f16.f16.f32 "
        "{%0,%1,%2,%3}, {%4,%5,%6,%7}, {%8,%9}, {%0,%1,%2,%3};"
        : "+f"(c[0]), "+f"(c[1]), "+f"(c[2]), "+f"(c[3])
        : "r"(a[0]), "r"(a[1]), "r"(a[2]), "r"(a[3]), "r"(b[0]), "r"(b[1]));
}

__device__ __forceinline__ int warp_incl_scan(int v) {
    int lane = threadIdx.x & 31;
#pragma unroll
    for (int o = 1; o < 32; o <<= 1) {
        int t = __shfl_up_sync(0xffffffffu, v, o);
        if (lane >= o) v += t;
    }
    return v;
}
__device__ __forceinline__ int block_incl_scan(int v, int* smem) {
    int lane = threadIdx.x & 31;
    int wid  = threadIdx.x >> 5;
    int nw   = blockDim.x >> 5;
    int s = warp_incl_scan(v);
    if (lane == 31) smem[wid] = s;
    __syncthreads();
    if (wid == 0) {
        int t = (lane < nw) ? smem[lane] : 0;
        t = warp_incl_scan(t);
        if (lane < nw) smem[lane] = t;
    }
    __syncthreads();
    int add = (wid > 0) ? smem[wid - 1] : 0;
    return s + add;
}
__device__ __forceinline__ int edge_at(const void* eidx, size_t idx) {
    if (d_is32) return ((const int*)eidx)[idx];
    return (int)((const long long*)eidx)[idx];
}

// fp32 x16 -> fp16 hi/lo pair-permuted x8
__device__ __forceinline__ void cvt16(const float* v, uint32_t* hp, uint32_t* lq) {
#pragma unroll
    for (int p = 0; p < 8; p++) {
        __half h0 = __float2half_rn(v[2 * p]);
        __half h1 = __float2half_rn(v[2 * p + 1]);
        float r0 = v[2 * p] - __half2float(h0);
        float r1 = v[2 * p + 1] - __half2float(h1);
        __half l0 = __float2half_rn(r0);
        __half l1 = __float2half_rn(r1);
        hp[p] = (uint32_t)__half_as_ushort(h0) | ((uint32_t)__half_as_ushort(h1) << 16);
        lq[p] = (uint32_t)__half_as_ushort(l0) | ((uint32_t)__half_as_ushort(l1) << 16);
    }
}

// ---------------- dtype detection ----------------
__global__ void detect_kernel(const void* eidx) {
    if (threadIdx.x == 0 && blockIdx.x == 0) {
        const long long* p = (const long long*)eidx;
        int is32 = 0;
        for (int i = 0; i < 64; i++) {
            long long v = p[i];
            if (v < 0 || v >= (long long)N_NODES) { is32 = 1; break; }
        }
        d_is32 = is32;
    }
}

// ---------------- A/W -> fp16 hi/lo, pair-permuted ----------------
__global__ void acvt_kernel(const float* __restrict__ A) {
    int gid = blockIdx.x * blockDim.x + threadIdx.x;
    if (gid >= N_NODES * (N_FEAT / 16)) return;
    float v[16];
#pragma unroll
    for (int i = 0; i < 4; i++) {
        float4 t = ((const float4*)(A + (size_t)gid * 16))[i];
        v[4 * i] = t.x; v[4 * i + 1] = t.y; v[4 * i + 2] = t.z; v[4 * i + 3] = t.w;
    }
    uint32_t hp[8], lq[8];
    cvt16(v, hp, lq);
    uint4* dh = (uint4*)d_ah + (size_t)gid * 2;
    uint4* dl = (uint4*)d_al + (size_t)gid * 2;
    dh[0] = make_uint4(hp[0], hp[4], hp[1], hp[5]);
    dh[1] = make_uint4(hp[2], hp[6], hp[3], hp[7]);
    dl[0] = make_uint4(lq[0], lq[4], lq[1], lq[5]);
    dl[1] = make_uint4(lq[2], lq[6], lq[3], lq[7]);
}
__global__ void wcvt_kernel(const float* __restrict__ W) {
    int gid = blockIdx.x * blockDim.x + threadIdx.x;
    if (gid >= N_HID * (N_FEAT / 16)) return;
    float v[16];
#pragma unroll
    for (int i = 0; i < 4; i++) {
        float4 t = ((const float4*)(W + (size_t)gid * 16))[i];
        v[4 * i] = t.x; v[4 * i + 1] = t.y; v[4 * i + 2] = t.z; v[4 * i + 3] = t.w;
    }
    uint32_t hp[8], lq[8];
    cvt16(v, hp, lq);
    uint4* dh = (uint4*)d_whp + (size_t)gid * 2;
    uint4* dl = (uint4*)d_wlp + (size_t)gid * 2;
    dh[0] = make_uint4(hp[0], hp[4], hp[1], hp[5]);
    dh[1] = make_uint4(hp[2], hp[6], hp[3], hp[7]);
    dl[0] = make_uint4(lq[0], lq[4], lq[1], lq[5]);
    dl[1] = make_uint4(lq[2], lq[6], lq[3], lq[7]);
}

// ---------------- graph build ----------------
__global__ void zero_kernel() {
    int i = blockIdx.x * blockDim.x + threadIdx.x;
    if (i < N_NODES) d_cursor[i] = 0;
    if (i < N_HID)   d_colsum[i] = 0.f;
}
__global__ void hist_kernel(const void* __restrict__ eidx) {
    int e = blockIdx.x * blockDim.x + threadIdx.x;
    if (e < N_EDGES) {
        int r = edge_at(eidx, (size_t)e);
        if ((unsigned)r < (unsigned)N_NODES)
            atomicAdd(&d_cursor[r], 1);
    }
}
__global__ void scan1_kernel() {
    __shared__ int smem[32];
    int i = blockIdx.x * 1024 + threadIdx.x;
    int c = (i < N_NODES) ? d_cursor[i] : 0;
    int s = block_incl_scan(c, smem);
    if (threadIdx.x == 1023) d_bsum[blockIdx.x] = s;
}
__global__ void scan2_kernel(int nblocks) {
    __shared__ int smem[32];
    int t = threadIdx.x;
    int v = (t < nblocks) ? d_bsum[t] : 0;
    int s = block_incl_scan(v, smem);
    if (t < nblocks) d_bsum[t] = s - v;  // exclusive
}
__global__ void scan3_kernel() {
    __shared__ int smem[32];
    int i = blockIdx.x * 1024 + threadIdx.x;
    int c = (i < N_NODES) ? d_cursor[i] : 0;
    int s = block_incl_scan(c, smem);
    int base = d_bsum[blockIdx.x];
    if (i < N_NODES) {
        int end = base + s;
        d_rowptr[i + 1] = end;
        d_cursor[i] = end - c;
    }
    if (i == 0) d_rowptr[0] = 0;
}
__global__ void scatter_kernel(const void* __restrict__ eidx,
                               const float* __restrict__ evals) {
    int e = blockIdx.x * blockDim.x + threadIdx.x;
    if (e < N_EDGES) {
        int r = edge_at(eidx, (size_t)e);
        int c = edge_at(eidx, (size_t)N_EDGES + e);
        if ((unsigned)r >= (unsigned)N_NODES) return;
        if ((unsigned)c >= (unsigned)N_NODES) c = 0;
        int p = atomicAdd(&d_cursor[r], 1);
        if ((unsigned)p < (unsigned)N_EDGES) {
            d_colidx[p] = c;
            d_eval[p]   = evals[e];
        }
    }
}

// ---------------- GEMM: mma.sync f16 3-term split (round-12 version) ----------------
#define SROW 24
#define BUFU (128 * SROW)
__global__ void __launch_bounds__(256, 1)
gemm_mma_kernel(const float* __restrict__ bias) {
    extern __shared__ uint32_t sm[];
    uint32_t* AH = sm;
    uint32_t* AL = sm + 2 * BUFU;
    uint32_t* BH = sm + 4 * BUFU;
    uint32_t* BL = sm + 6 * BUFU;
    const uint32_t sbase = smem_u32p(sm);

    const int tid = threadIdx.x, lane = tid & 31, wid = tid >> 5;
    const int m0 = blockIdx.y * 128, n0 = blockIdx.x * 128;
    const int g = lane >> 2, tq = lane & 3;
    const int wm = (wid >> 1) * 32, wn = (wid & 1) * 64;

    const int lr = tid >> 1;
    const int lp = tid & 1;
    int arow = m0 + lr; if (arow >= N_NODES) arow = N_NODES - 1;
    const uint32_t* agh = d_ah + (size_t)arow * 256 + lp * 8;
    const uint32_t* agl = d_al + (size_t)arow * 256 + lp * 8;
    const uint32_t* bgh = d_whp + (size_t)(n0 + lr) * 256 + lp * 8;
    const uint32_t* bgl = d_wlp + (size_t)(n0 + lr) * 256 + lp * 8;
    const uint32_t sdst = (uint32_t)(lr * SROW + lp * 8) * 4;

    float acc[2][8][4];
#pragma unroll
    for (int mt = 0; mt < 2; mt++)
#pragma unroll
        for (int nt = 0; nt < 8; nt++)
#pragma unroll
            for (int c = 0; c < 4; c++) acc[mt][nt][c] = 0.f;

#define PREFETCH(kc, b) do { \
    uint32_t o = sbase + (uint32_t)(b) * (BUFU * 4) + sdst; \
    const uint32_t ksrc = (uint32_t)(kc) * 16; \
    cpa16(o,                    agh + ksrc); cpa16(o + 16,                    agh + ksrc + 4); \
    cpa16(o + 2 * BUFU * 4,     agl + ksrc); cpa16(o + 2 * BUFU * 4 + 16,     agl + ksrc + 4); \
    cpa16(o + 4 * BUFU * 4,     bgh + ksrc); cpa16(o + 4 * BUFU * 4 + 16,     bgh + ksrc + 4); \
    cpa16(o + 6 * BUFU * 4,     bgl + ksrc); cpa16(o + 6 * BUFU * 4 + 16,     bgl + ksrc + 4); \
} while (0)

    PREFETCH(0, 0);
    cpa_commit();

    for (int kc = 0; kc < N_FEAT / 32; kc++) {
        if (kc < N_FEAT / 32 - 1) {
            PREFETCH(kc + 1, (kc + 1) & 1);
            cpa_commit();
            asm volatile("cp.async.wait_group 1;" ::: "memory");
        } else {
            asm volatile("cp.async.wait_group 0;" ::: "memory");
        }
        __syncthreads();

        const uint32_t bb = (uint32_t)(kc & 1) * BUFU;
#pragma unroll
        for (int kk = 0; kk < 2; kk++) {
            const int kb = kk * 8 + 2 * tq;
            uint32_t ah[2][4], al[2][4], bh[8][2], bl[8][2];
#pragma unroll
            for (int mt = 0; mt < 2; mt++) {
                int r = wm + mt * 16 + g;
                u64 t0 = *(const u64*)(AH + bb + r * SROW + kb);
                u64 t1 = *(const u64*)(AH + bb + (r + 8) * SROW + kb);
                ah[mt][0] = (uint32_t)t0; ah[mt][2] = (uint32_t)(t0 >> 32);
                ah[mt][1] = (uint32_t)t1; ah[mt][3] = (uint32_t)(t1 >> 32);
                u64 s0 = *(const u64*)(AL + bb + r * SROW + kb);
                u64 s1 = *(const u64*)(AL + bb + (r + 8) * SROW + kb);
                al[mt][0] = (uint32_t)s0; al[mt][2] = (uint32_t)(s0 >> 32);
                al[mt][1] = (uint32_t)s1; al[mt][3] = (uint32_t)(s1 >> 32);
            }
#pragma unroll
            for (int nt = 0; nt < 8; nt++) {
                int r = wn + nt * 8 + g;
                u64 t = *(const u64*)(BH + bb + r * SROW + kb);
                bh[nt][0] = (uint32_t)t; bh[nt][1] = (uint32_t)(t >> 32);
                u64 s = *(const u64*)(BL + bb + r * SROW + kb);
                bl[nt][0] = (uint32_t)s; bl[nt][1] = (uint32_t)(s >> 32);
            }
#pragma unroll
            for (int mt = 0; mt < 2; mt++)
#pragma unroll
                for (int nt = 0; nt < 8; nt++) {
                    mma_f16(acc[mt][nt], ah[mt], bh[nt]);
                    mma_f16(acc[mt][nt], al[mt], bh[nt]);
                    mma_f16(acc[mt][nt], ah[mt], bl[nt]);
                }
        }
        __syncthreads();
    }
#undef PREFETCH

    // epilogue: bias add then pack fp16x2 into d_hh
#pragma unroll
    for (int mt = 0; mt < 2; mt++) {
        int r0 = m0 + wm + mt * 16 + g;
        int r1 = r0 + 8;
#pragma unroll
        for (int nt = 0; nt < 8; nt++) {
            int col = n0 + wn + nt * 8 + 2 * tq;
            float2 b = *(const float2*)&bias[col];
            int pidx = col >> 1;
            if (r0 < N_NODES) {
                __half2 o = __floats2half2_rn(acc[mt][nt][0] + b.x, acc[mt][nt][1] + b.y);
                d_hh[(size_t)r0 * (N_HID / 2) + pidx] = *(uint32_t*)&o;
            }
            if (r1 < N_NODES) {
                __half2 o = __floats2half2_rn(acc[mt][nt][2] + b.x, acc[mt][nt][3] + b.y);
                d_hh[(size_t)r1 * (N_HID / 2) + pidx] = *(uint32_t*)&o;
            }
        }
    }
}

// ---------------- SpMM body (fp16 gather, fp32 accumulate) ----------------
__device__ __forceinline__ void spmm_row(int node, int j, float a0, float& ax, float& ay) {
    const int beg = d_rowptr[node];
    const int end = d_rowptr[node + 1];
    ax = 0.f; ay = 0.f;
    int e = beg;
    for (; e + 4 <= end; e += 4) {
        int c0 = d_colidx[e], c1 = d_colidx[e + 1];
        int c2 = d_colidx[e + 2], c3 = d_colidx[e + 3];
        float w0 = d_eval[e], w1 = d_eval[e + 1];
        float w2 = d_eval[e + 2], w3 = d_eval[e + 3];
        uint32_t p0 = d_hh[(size_t)c0 * (N_HID / 2) + j];
        uint32_t p1 = d_hh[(size_t)c1 * (N_HID / 2) + j];
        uint32_t p2 = d_hh[(size_t)c2 * (N_HID / 2) + j];
        uint32_t p3 = d_hh[(size_t)c3 * (N_HID / 2) + j];
        float2 v0 = __half22float2(*(__half2*)&p0);
        float2 v1 = __half22float2(*(__half2*)&p1);
        float2 v2 = __half22float2(*(__half2*)&p2);
        float2 v3 = __half22float2(*(__half2*)&p3);
        ax += w0 * v0.x; ay += w0 * v0.y;
        ax += w1 * v1.x; ay += w1 * v1.y;
        ax += w2 * v2.x; ay += w2 * v2.y;
        ax += w3 * v3.x; ay += w3 * v3.y;
    }
    for (; e < end; ++e) {
        int c = d_colidx[e];
        float w = d_eval[e];
        uint32_t p = d_hh[(size_t)c * (N_HID / 2) + j];
        float2 v = __half22float2(*(__half2*)&p);
        ax += w * v.x; ay += w * v.y;
    }
    ax = (ax >= 0.f) ? ax : a0 * ax;
    ay = (ay >= 0.f) ? ay : a0 * ay;
}

// graph 1: write g (fp16x2)
__global__ __launch_bounds__(128)
void spmm_kernel(const float* __restrict__ prelu_a) {
    const int node = blockIdx.x;
    const int j = threadIdx.x;
    float ax, ay;
    spmm_row(node, j, prelu_a[0], ax, ay);
    __half2 o = __floats2half2_rn(ax, ay);
    d_gh[(size_t)node * (N_HID / 2) + j] = *(uint32_t*)&o;
}

// graph 2: fused score (v already computed from graph 1)
__global__ __launch_bounds__(128)
void spmm_score_kernel(const float* __restrict__ prelu_a,
                       const float* __restrict__ bb, float* __restrict__ out) {
    __shared__ float red[4];
    const int node = blockIdx.x;
    const int j = threadIdx.x;
    const int lane = j & 31, warp = j >> 5;
    float ax, ay;
    spmm_row(node, j, prelu_a[0], ax, ay);
    float2 vv = *(const float2*)&d_v[2 * j];
    float dot = ax * vv.x + ay * vv.y;
#pragma unroll
    for (int o = 16; o > 0; o >>= 1) dot += __shfl_xor_sync(0xffffffffu, dot, o);
    if (lane == 0) red[warp] = dot;
    __syncthreads();
    if (j == 0) out[node] = red[0] + red[1] + red[2] + red[3] + bb[0];
}

// ---------------- column sum (fp16 g) / v / score (graph 1) ----------------
__global__ __launch_bounds__(128)
void colsum_kernel() {
    const int j = threadIdx.x;          // 0..127 (column pair)
    const int start = blockIdx.x * 512;
    int stop = start + 512;
    if (stop > N_NODES) stop = N_NODES;
    float sx = 0.f, sy = 0.f;
    for (int n = start; n < stop; n++) {
        uint32_t p = d_gh[(size_t)n * (N_HID / 2) + j];
        float2 v = __half22float2(*(__half2*)&p);
        sx += v.x; sy += v.y;
    }
    atomicAdd(&d_colsum[2 * j], sx);
    atomicAdd(&d_colsum[2 * j + 1], sy);
}
__global__ void vker(const float* __restrict__ bw) {
    __shared__ float ssig[N_HID];
    int t = threadIdx.x;
    ssig[t] = 1.f / (1.f + expf(-d_colsum[t] * (1.f / (float)N_NODES)));
    __syncthreads();
    float acc = 0.f;
#pragma unroll 8
    for (int g = 0; g < N_HID; g++) acc += bw[t * N_HID + g] * ssig[g];
    d_v[t] = acc;
}
__global__ __launch_bounds__(256)
void score_kernel(const float* __restrict__ bb, float* __restrict__ out) {
    const int warp = threadIdx.x >> 5;
    const int lane = threadIdx.x & 31;
    const int node = blockIdx.x * 8 + warp;
    if (node >= N_NODES) return;
    // lane reads one uint4 = 4 fp16x2 pairs = columns 8*lane..8*lane+7
    uint4 gp = ((const uint4*)&d_gh[(size_t)node * (N_HID / 2)])[lane];
    const float4* vv = (const float4*)d_v;
    float4 va = vv[2 * lane];
    float4 vb = vv[2 * lane + 1];
    float2 g0 = __half22float2(*(__half2*)&gp.x);
    float2 g1 = __half22float2(*(__half2*)&gp.y);
    float2 g2 = __half22float2(*(__half2*)&gp.z);
    float2 g3 = __half22float2(*(__half2*)&gp.w);
    float acc = g0.x * va.x + g0.y * va.y + g1.x * va.z + g1.y * va.w
              + g2.x * vb.x + g2.y * vb.y + g3.x * vb.z + g3.y * vb.w;
#pragma unroll
    for (int o = 16; o > 0; o >>= 1) acc += __shfl_xor_sync(0xffffffffu, acc, o);
    if (lane == 0) out[node] = acc + bb[0];
}

// ---------------- launch ----------------
extern "C" void kernel_launch(void* const* d_in, const int* in_sizes, int n_in,
                              void* d_out, int out_size) {
    const float* x1  = (const float*)d_in[0];
    const float* x2  = (const float*)d_in[1];
    const float* ev  = (const float*)d_in[2];
    const float* fcw = (const float*)d_in[3];
    const float* fcb = (const float*)d_in[4];
    const float* pa  = (const float*)d_in[5];
    const float* bw  = (const float*)d_in[6];
    const float* bb  = (const float*)d_in[7];
    const void*  ei  = (const void*)d_in[8];
    float* out = (float*)d_out;

    const int GEMM_SMEM = 8 * BUFU * 4;   // 98304 bytes
    static int smem_set = 0;
    if (!smem_set) {
        cudaFuncSetAttribute(gemm_mma_kernel,
                             cudaFuncAttributeMaxDynamicSharedMemorySize, GEMM_SMEM);
        smem_set = 1;
    }

    const int scan_blocks = (N_NODES + 1023) / 1024;
    const int edge_blocks = (N_EDGES + 255) / 256;
    const int agrp_blocks = (N_NODES * (N_FEAT / 16) + 255) / 256;
    const int wgrp_blocks = (N_HID * (N_FEAT / 16) + 255) / 256;
    dim3 ggrid(N_HID / 128, (N_NODES + 127) / 128);

    // CSR build + W conversion
    detect_kernel<<<1, 32>>>(ei);
    wcvt_kernel<<<wgrp_blocks, 256>>>(fcw);
    zero_kernel<<<(N_NODES + 255) / 256, 256>>>();
    hist_kernel<<<edge_blocks, 256>>>(ei);
    scan1_kernel<<<scan_blocks, 1024>>>();
    scan2_kernel<<<1, 128>>>(scan_blocks);
    scan3_kernel<<<scan_blocks, 1024>>>();
    scatter_kernel<<<edge_blocks, 256>>>(ei, ev);

    // graph 1
    acvt_kernel<<<agrp_blocks, 256>>>(x1);
    gemm_mma_kernel<<<ggrid, 256, GEMM_SMEM>>>(fcb);
    spmm_kernel<<<N_NODES, 128>>>(pa);
    colsum_kernel<<<(N_NODES + 511) / 512, 128>>>();
    vker<<<1, N_HID>>>(bw);
    score_kernel<<<(N_NODES + 7) / 8, 256>>>(bb, out);

    // graph 2 (fused spmm+score; no g traffic)
    acvt_kernel<<<agrp_blocks, 256>>>(x2);
    gemm_mma_kernel<<<ggrid, 256, GEMM_SMEM>>>(fcb);
    spmm_score_kernel<<<N_NODES, 128>>>(pa, bb, out + N_NODES);
}